// round 1
// baseline (speedup 1.0000x reference)
#include <cuda_runtime.h>
#include <math.h>

#define B_   16
#define L_   50
#define P_   49
#define T_   20
#define D_   512
#define H_   8
#define DH_  64
#define DFF_ 2048

#define ROWS_IMG (B_*L_*T_)            // 16000
#define ROWS_TIT (B_*L_*P_)            // 39200
#define ROWS_ALL (ROWS_IMG+ROWS_TIT)   // 55200

// ---------------------------------------------------------------------------
// Scratch (device globals: allocation-free, graph-capturable)
// ---------------------------------------------------------------------------
__device__ float g_attn[(size_t)ROWS_ALL * D_];   // attention output (pre-proj), img rows then tit rows
__device__ float g_hid [(size_t)ROWS_ALL * D_];   // after proj (residual source)
__device__ float g_ffh [(size_t)ROWS_TIT * DFF_]; // gelu intermediate (reused img then tit)
__device__ float g_ffo [(size_t)ROWS_TIT * D_];   // ffn output (reused img then tit)

// ---------------------------------------------------------------------------
// Fused attention: one CTA per (b*l, h)
// ---------------------------------------------------------------------------
__global__ void __launch_bounds__(256) attn_kernel(
    const float* __restrict__ img,
    const float* __restrict__ title,
    const int*   __restrict__ mask,
    const float* __restrict__ scale_img,
    const float* __restrict__ scale_title,
    float*       __restrict__ attn_cat)
{
    const int h   = blockIdx.x & (H_-1);
    const int bl  = blockIdx.x >> 3;
    const int tid = threadIdx.x;

    __shared__ float im[P_][DH_+1];
    __shared__ float ti[T_][DH_+1];
    __shared__ float raw[P_][T_];
    __shared__ float pim[P_][T_];
    __shared__ float pti[T_][P_+3];
    __shared__ float s_si[P_];
    __shared__ float s_st[T_];
    __shared__ int   mk[T_];

    const float* ib = img   + (size_t)bl * (P_*D_) + h*DH_;
    for (int idx = tid; idx < P_*DH_; idx += 256) {
        int p = idx >> 6, d = idx & 63;
        im[p][d] = ib[p*D_ + d];
    }
    const float* tb = title + (size_t)bl * (T_*D_) + h*DH_;
    for (int idx = tid; idx < T_*DH_; idx += 256) {
        int t = idx >> 6, d = idx & 63;
        ti[t][d] = tb[t*D_ + d];
    }
    if (tid < T_) { mk[tid] = mask[bl*T_ + tid]; s_st[tid] = scale_title[h*T_ + tid]; }
    if (tid < P_) s_si[tid] = scale_img[h*P_ + tid];
    __syncthreads();

    // raw[p][t] = <im_p, ti_t> / sqrt(64)
    for (int idx = tid; idx < P_*T_; idx += 256) {
        int p = idx / T_, t = idx % T_;
        float s = 0.f;
        #pragma unroll 16
        for (int d = 0; d < DH_; d++) s += im[p][d] * ti[t][d];
        raw[p][t] = s * 0.125f;
    }
    __syncthreads();

    // p_img: softmax over t of raw[p][t]*scale_img[h,p], mask by t
    if (tid < P_) {
        const int p = tid;
        const float sc = s_si[p];
        float v[T_];
        float mx = -3.4e38f;
        #pragma unroll
        for (int t = 0; t < T_; t++) {
            float x = mk[t] ? raw[p][t]*sc : -1e9f;
            v[t] = x;
            mx = fmaxf(mx, x);
        }
        float s = 0.f;
        #pragma unroll
        for (int t = 0; t < T_; t++) { float e = expf(v[t]-mx); v[t]=e; s+=e; }
        float inv = 1.f/s;
        #pragma unroll
        for (int t = 0; t < T_; t++) pim[p][t] = v[t]*inv;
    }
    // p_tit: softmax over p of raw[p][t]*scale_title[h,t], whole row masked when mk[t]==0
    if (tid >= 64 && tid < 64+T_) {
        const int t = tid - 64;
        const float sc = s_st[t];
        const bool valid = (mk[t] != 0);
        float mx = -3.4e38f;
        for (int p = 0; p < P_; p++) {
            float x = valid ? raw[p][t]*sc : -1e9f;
            pti[t][p] = x;
            mx = fmaxf(mx, x);
        }
        float s = 0.f;
        for (int p = 0; p < P_; p++) { float e = expf(pti[t][p]-mx); pti[t][p]=e; s+=e; }
        float inv = 1.f/s;
        for (int p = 0; p < P_; p++) pti[t][p] *= inv;
    }
    __syncthreads();

    // hid_tit[p,d] = sum_t pim[p][t] * ti[t][d]   -> rows [ROWS_IMG + bl*P_ + p]
    for (int idx = tid; idx < P_*DH_; idx += 256) {
        int p = idx >> 6, d = idx & 63;
        float s = 0.f;
        #pragma unroll
        for (int t = 0; t < T_; t++) s += pim[p][t]*ti[t][d];
        attn_cat[(size_t)(ROWS_IMG + bl*P_ + p)*D_ + h*DH_ + d] = s;
    }
    // hid_img[t,d] = sum_p pti[t][p] * im[p][d]   -> rows [bl*T_ + t]
    for (int idx = tid; idx < T_*DH_; idx += 256) {
        int t = idx >> 6, d = idx & 63;
        float s = 0.f;
        #pragma unroll 7
        for (int p = 0; p < P_; p++) s += pti[t][p]*im[p][d];
        attn_cat[(size_t)(bl*T_ + t)*D_ + h*DH_ + d] = s;
    }
}

// ---------------------------------------------------------------------------
// Tiled fp32 GEMM: C[M,N] = A[M,K] * W[N,K]^T + bias (optional tanh-GELU)
// BM=BN=128, BK=8, 256 threads, 8x8 per thread, register prefetch
// ---------------------------------------------------------------------------
__device__ __forceinline__ float gelu_t(float x) {
    float x3 = x*x*x;
    return 0.5f*x*(1.f + tanhf(0.7978845608028654f*(x + 0.044715f*x3)));
}

template<int ACT>
__global__ void __launch_bounds__(256, 2) gemm_kernel(
    const float* __restrict__ A, const float* __restrict__ W,
    const float* __restrict__ bias, float* __restrict__ C,
    int M, int N, int K)
{
    __shared__ float As[8][128];
    __shared__ float Ws[8][128];

    const int tid = threadIdx.x;
    const int tx = tid & 15, ty = tid >> 4;
    const int lr = tid >> 1;          // 0..127
    const int lc = (tid & 1) * 4;     // 0 or 4

    const int bm = blockIdx.x * 128;
    const int bn = blockIdx.y * 128;

    const int  gmL = bm + lr;
    const bool aok = gmL < M;
    const float* Ap = A + (size_t)gmL * K + lc;
    const float* Wp = W + (size_t)(bn + lr) * K + lc;

    float acc[8][8] = {};

    float4 aR = aok ? *(const float4*)Ap : make_float4(0.f,0.f,0.f,0.f);
    float4 wR = *(const float4*)Wp;

    for (int k0 = 0; k0 < K; k0 += 8) {
        As[lc+0][lr]=aR.x; As[lc+1][lr]=aR.y; As[lc+2][lr]=aR.z; As[lc+3][lr]=aR.w;
        Ws[lc+0][lr]=wR.x; Ws[lc+1][lr]=wR.y; Ws[lc+2][lr]=wR.z; Ws[lc+3][lr]=wR.w;
        __syncthreads();
        if (k0 + 8 < K) {
            aR = aok ? *(const float4*)(Ap + k0 + 8) : make_float4(0.f,0.f,0.f,0.f);
            wR = *(const float4*)(Wp + k0 + 8);
        }
        #pragma unroll
        for (int kk = 0; kk < 8; kk++) {
            float a[8], w[8];
            *(float4*)&a[0] = *(const float4*)&As[kk][ty*8];
            *(float4*)&a[4] = *(const float4*)&As[kk][ty*8+4];
            *(float4*)&w[0] = *(const float4*)&Ws[kk][tx*8];
            *(float4*)&w[4] = *(const float4*)&Ws[kk][tx*8+4];
            #pragma unroll
            for (int i = 0; i < 8; i++)
                #pragma unroll
                for (int j = 0; j < 8; j++)
                    acc[i][j] = fmaf(a[i], w[j], acc[i][j]);
        }
        __syncthreads();
    }

    float bv[8];
    #pragma unroll
    for (int j = 0; j < 8; j++) bv[j] = bias[bn + tx*8 + j];

    #pragma unroll
    for (int i = 0; i < 8; i++) {
        int gm = bm + ty*8 + i;
        if (gm < M) {
            #pragma unroll
            for (int j = 0; j < 8; j += 4) {
                float4 v;
                v.x = acc[i][j+0] + bv[j+0];
                v.y = acc[i][j+1] + bv[j+1];
                v.z = acc[i][j+2] + bv[j+2];
                v.w = acc[i][j+3] + bv[j+3];
                if (ACT) { v.x=gelu_t(v.x); v.y=gelu_t(v.y); v.z=gelu_t(v.z); v.w=gelu_t(v.w); }
                *(float4*)&C[(size_t)gm*N + bn + tx*8 + j] = v;
            }
        }
    }
}

// ---------------------------------------------------------------------------
// out[row] = hid[row] + a*(x-mean)/(std(ddof=1)+eps) + b     (x = ffn[row])
// 128 threads per row, each owns one float4 (512 elements)
// ---------------------------------------------------------------------------
__global__ void __launch_bounds__(128) ln_res_kernel(
    const float* __restrict__ hid, const float* __restrict__ ffn,
    const float* __restrict__ ga,  const float* __restrict__ gb,
    float* __restrict__ out)
{
    const int row = blockIdx.x;
    const int tid = threadIdx.x;
    float4 xv = ((const float4*)(ffn + (size_t)row*D_))[tid];
    float s = xv.x + xv.y + xv.z + xv.w;
    float q = xv.x*xv.x + xv.y*xv.y + xv.z*xv.z + xv.w*xv.w;
    #pragma unroll
    for (int o = 16; o > 0; o >>= 1) {
        s += __shfl_xor_sync(0xffffffffu, s, o);
        q += __shfl_xor_sync(0xffffffffu, q, o);
    }
    __shared__ float ss[4], sq[4];
    if ((tid & 31) == 0) { ss[tid>>5] = s; sq[tid>>5] = q; }
    __syncthreads();
    float S = ss[0]+ss[1]+ss[2]+ss[3];
    float Q = sq[0]+sq[1]+sq[2]+sq[3];
    float mean = S * (1.f/D_);
    float var  = (Q - (float)D_*mean*mean) * (1.f/(D_-1));
    var = fmaxf(var, 0.f);
    float inv = 1.f / (sqrtf(var) + 1e-6f);

    float4 hv = ((const float4*)(hid + (size_t)row*D_))[tid];
    float4 av = ((const float4*)ga)[tid];
    float4 bv = ((const float4*)gb)[tid];
    float4 o4;
    o4.x = hv.x + av.x*(xv.x-mean)*inv + bv.x;
    o4.y = hv.y + av.y*(xv.y-mean)*inv + bv.y;
    o4.z = hv.z + av.z*(xv.z-mean)*inv + bv.z;
    o4.w = hv.w + av.w*(xv.w-mean)*inv + bv.w;
    ((float4*)(out + (size_t)row*D_))[tid] = o4;
}

// ---------------------------------------------------------------------------
extern "C" void kernel_launch(void* const* d_in, const int* in_sizes, int n_in,
                              void* d_out, int out_size)
{
    const float* img    = (const float*)d_in[0];
    const float* title  = (const float*)d_in[1];
    const int*   mask   = (const int*)  d_in[2];
    const float* s_img  = (const float*)d_in[3];
    const float* s_tit  = (const float*)d_in[4];
    const float* w_proj = (const float*)d_in[5];
    const float* b_proj = (const float*)d_in[6];
    const float* w1i    = (const float*)d_in[7];
    const float* b1i    = (const float*)d_in[8];
    const float* w2i    = (const float*)d_in[9];
    const float* b2i    = (const float*)d_in[10];
    const float* w1t    = (const float*)d_in[11];
    const float* b1t    = (const float*)d_in[12];
    const float* w2t    = (const float*)d_in[13];
    const float* b2t    = (const float*)d_in[14];
    const float* lai    = (const float*)d_in[15];
    const float* lbi    = (const float*)d_in[16];
    const float* lat    = (const float*)d_in[17];
    const float* lbt    = (const float*)d_in[18];
    float* out = (float*)d_out;

    float *attn, *hid, *ffh, *ffo;
    cudaGetSymbolAddress((void**)&attn, g_attn);
    cudaGetSymbolAddress((void**)&hid,  g_hid);
    cudaGetSymbolAddress((void**)&ffh,  g_ffh);
    cudaGetSymbolAddress((void**)&ffo,  g_ffo);

    // 1) fused attention -> concatenated activations (img rows, then tit rows)
    attn_kernel<<<B_*L_*H_, 256>>>(img, title, mask, s_img, s_tit, attn);

    // 2) shared projection over all 55200 rows
    dim3 gP((ROWS_ALL+127)/128, D_/128);
    gemm_kernel<0><<<gP, 256>>>(attn, w_proj, b_proj, hid, ROWS_ALL, D_, D_);

    // 3) img FFN + LN+residual
    dim3 g1i((ROWS_IMG+127)/128, DFF_/128);
    gemm_kernel<1><<<g1i, 256>>>(hid, w1i, b1i, ffh, ROWS_IMG, DFF_, D_);
    dim3 g2i((ROWS_IMG+127)/128, D_/128);
    gemm_kernel<0><<<g2i, 256>>>(ffh, w2i, b2i, ffo, ROWS_IMG, D_, DFF_);
    ln_res_kernel<<<ROWS_IMG, 128>>>(hid, ffo, lai, lbi, out);

    // 4) tit FFN + LN+residual
    const float* hidT = hid + (size_t)ROWS_IMG*D_;
    dim3 g1t((ROWS_TIT+127)/128, DFF_/128);
    gemm_kernel<1><<<g1t, 256>>>(hidT, w1t, b1t, ffh, ROWS_TIT, DFF_, D_);
    dim3 g2t((ROWS_TIT+127)/128, D_/128);
    gemm_kernel<0><<<g2t, 256>>>(ffh, w2t, b2t, ffo, ROWS_TIT, D_, DFF_);
    ln_res_kernel<<<ROWS_TIT, 128>>>(hidT, ffo, lat, lbt, out + (size_t)ROWS_IMG*D_);
}

// round 2
// speedup vs baseline: 1.9598x; 1.9598x over previous
#include <cuda_runtime.h>
#include <math.h>
#include <stdint.h>

#define B_   16
#define L_   50
#define P_   49
#define T_   20
#define D_   512
#define H_   8
#define DH_  64
#define DFF_ 2048

#define ROWS_IMG (B_*L_*T_)            // 16000
#define ROWS_TIT (B_*L_*P_)            // 39200
#define ROWS_ALL (ROWS_IMG+ROWS_TIT)   // 55200

// ---------------------------------------------------------------------------
// Scratch (device globals: allocation-free, graph-capturable)
// ---------------------------------------------------------------------------
__device__ float g_attn[(size_t)ROWS_ALL * D_];
__device__ float g_hid [(size_t)ROWS_ALL * D_];
__device__ float g_ffh [(size_t)ROWS_TIT * DFF_];
__device__ float g_ffo [(size_t)ROWS_TIT * D_];

// ---------------------------------------------------------------------------
// Fused attention: one CTA per (b*l, h)
// ---------------------------------------------------------------------------
__global__ void __launch_bounds__(256) attn_kernel(
    const float* __restrict__ img,
    const float* __restrict__ title,
    const int*   __restrict__ mask,
    const float* __restrict__ scale_img,
    const float* __restrict__ scale_title,
    float*       __restrict__ attn_cat)
{
    const int h   = blockIdx.x & (H_-1);
    const int bl  = blockIdx.x >> 3;
    const int tid = threadIdx.x;

    __shared__ float im[P_][DH_+1];
    __shared__ float ti[T_][DH_+1];
    __shared__ float raw[P_][T_];
    __shared__ float pim[P_][T_];
    __shared__ float pti[T_][P_+3];
    __shared__ float s_si[P_];
    __shared__ float s_st[T_];
    __shared__ int   mk[T_];

    const float* ib = img   + (size_t)bl * (P_*D_) + h*DH_;
    for (int idx = tid; idx < P_*DH_; idx += 256) {
        int p = idx >> 6, d = idx & 63;
        im[p][d] = ib[p*D_ + d];
    }
    const float* tb = title + (size_t)bl * (T_*D_) + h*DH_;
    for (int idx = tid; idx < T_*DH_; idx += 256) {
        int t = idx >> 6, d = idx & 63;
        ti[t][d] = tb[t*D_ + d];
    }
    if (tid < T_) { mk[tid] = mask[bl*T_ + tid]; s_st[tid] = scale_title[h*T_ + tid]; }
    if (tid < P_) s_si[tid] = scale_img[h*P_ + tid];
    __syncthreads();

    for (int idx = tid; idx < P_*T_; idx += 256) {
        int p = idx / T_, t = idx % T_;
        float s = 0.f;
        #pragma unroll 16
        for (int d = 0; d < DH_; d++) s += im[p][d] * ti[t][d];
        raw[p][t] = s * 0.125f;
    }
    __syncthreads();

    if (tid < P_) {
        const int p = tid;
        const float sc = s_si[p];
        float v[T_];
        float mx = -3.4e38f;
        #pragma unroll
        for (int t = 0; t < T_; t++) {
            float x = mk[t] ? raw[p][t]*sc : -1e9f;
            v[t] = x;
            mx = fmaxf(mx, x);
        }
        float s = 0.f;
        #pragma unroll
        for (int t = 0; t < T_; t++) { float e = expf(v[t]-mx); v[t]=e; s+=e; }
        float inv = 1.f/s;
        #pragma unroll
        for (int t = 0; t < T_; t++) pim[p][t] = v[t]*inv;
    }
    if (tid >= 64 && tid < 64+T_) {
        const int t = tid - 64;
        const float sc = s_st[t];
        const bool valid = (mk[t] != 0);
        float mx = -3.4e38f;
        for (int p = 0; p < P_; p++) {
            float x = valid ? raw[p][t]*sc : -1e9f;
            pti[t][p] = x;
            mx = fmaxf(mx, x);
        }
        float s = 0.f;
        for (int p = 0; p < P_; p++) { float e = expf(pti[t][p]-mx); pti[t][p]=e; s+=e; }
        float inv = 1.f/s;
        for (int p = 0; p < P_; p++) pti[t][p] *= inv;
    }
    __syncthreads();

    for (int idx = tid; idx < P_*DH_; idx += 256) {
        int p = idx >> 6, d = idx & 63;
        float s = 0.f;
        #pragma unroll
        for (int t = 0; t < T_; t++) s += pim[p][t]*ti[t][d];
        attn_cat[(size_t)(ROWS_IMG + bl*P_ + p)*D_ + h*DH_ + d] = s;
    }
    for (int idx = tid; idx < T_*DH_; idx += 256) {
        int t = idx >> 6, d = idx & 63;
        float s = 0.f;
        #pragma unroll 7
        for (int p = 0; p < P_; p++) s += pti[t][p]*im[p][d];
        attn_cat[(size_t)(bl*T_ + t)*D_ + h*DH_ + d] = s;
    }
}

// ---------------------------------------------------------------------------
// TF32 tensor-core GEMM: C[M,N] = A[M,K]*W[N,K]^T + bias (opt. tanh-GELU)
// BM=BN=128, BK=16, 4 warps x (64x64 warp tile), mma.sync m16n8k8 tf32
// cp.async double-buffered staging, smem [row][k] pitch 20 (conflict-free)
// ---------------------------------------------------------------------------
__device__ __forceinline__ float gelu_t(float x) {
    float x3 = x*x*x;
    return 0.5f*x*(1.f + tanhf(0.7978845608028654f*(x + 0.044715f*x3)));
}

__device__ __forceinline__ uint32_t f2tf(float x) {
    uint32_t u;
    asm("cvt.rna.tf32.f32 %0, %1;" : "=r"(u) : "f"(x));
    return u;
}

__device__ __forceinline__ void mma_tf32(float* d, const uint32_t* a, const uint32_t* b) {
    asm volatile(
        "mma.sync.aligned.m16n8k8.row.col.f32.tf32.tf32.f32 "
        "{%0,%1,%2,%3}, {%4,%5,%6,%7}, {%8,%9}, {%0,%1,%2,%3};"
        : "+f"(d[0]), "+f"(d[1]), "+f"(d[2]), "+f"(d[3])
        : "r"(a[0]), "r"(a[1]), "r"(a[2]), "r"(a[3]), "r"(b[0]), "r"(b[1]));
}

__device__ __forceinline__ void cp16(void* smem_dst, const void* gsrc) {
    uint32_t d = (uint32_t)__cvta_generic_to_shared(smem_dst);
    asm volatile("cp.async.cg.shared.global [%0], [%1], 16;" :: "r"(d), "l"(gsrc));
}

#define SPITCH 20

template<int ACT>
__global__ void __launch_bounds__(128, 2) gemm_tc(
    const float* __restrict__ A, const float* __restrict__ W,
    const float* __restrict__ bias, float* __restrict__ C,
    int M, int N, int K)
{
    __shared__ float As[2][128][SPITCH];
    __shared__ float Ws[2][128][SPITCH];

    const int tid  = threadIdx.x;
    const int lane = tid & 31;
    const int warp = tid >> 5;
    const int wm   = warp >> 1;     // 0..1
    const int wn   = warp & 1;      // 0..1

    const int bn = blockIdx.x * 128;
    const int bm = blockIdx.y * 128;

    const int  arow = bm + tid;
    const bool aok  = arow < M;
    const float* Ap = A + (size_t)arow * K;
    const float* Wp = W + (size_t)(bn + tid) * K;

    // zero-fill rows of OOB threads once (buffers never overwritten by them)
    if (!aok) {
        #pragma unroll
        for (int b = 0; b < 2; b++)
            #pragma unroll
            for (int j = 0; j < 16; j++)
                As[b][tid][j] = 0.f;
    }

    float acc[4][8][4];
    #pragma unroll
    for (int mt = 0; mt < 4; mt++)
        #pragma unroll
        for (int nt = 0; nt < 8; nt++)
            #pragma unroll
            for (int r = 0; r < 4; r++) acc[mt][nt][r] = 0.f;

    // prologue: stage tile 0
    if (aok) {
        #pragma unroll
        for (int j = 0; j < 4; j++) cp16(&As[0][tid][j*4], Ap + j*4);
    }
    #pragma unroll
    for (int j = 0; j < 4; j++) cp16(&Ws[0][tid][j*4], Wp + j*4);
    asm volatile("cp.async.commit_group;");

    const int KT = K >> 4;
    const int mrow = wm*64 + (lane >> 2);
    const int nrow = wn*64 + (lane >> 2);

    for (int kt = 0; kt < KT; kt++) {
        const int cur = kt & 1;
        asm volatile("cp.async.wait_group 0;");
        __syncthreads();

        if (kt + 1 < KT) {
            const int nb = (kt + 1) & 1;
            const int ko = (kt + 1) << 4;
            if (aok) {
                #pragma unroll
                for (int j = 0; j < 4; j++) cp16(&As[nb][tid][j*4], Ap + ko + j*4);
            }
            #pragma unroll
            for (int j = 0; j < 4; j++) cp16(&Ws[nb][tid][j*4], Wp + ko + j*4);
            asm volatile("cp.async.commit_group;");
        }

        #pragma unroll
        for (int ks = 0; ks < 16; ks += 8) {
            const int kb = ks + (lane & 3);
            uint32_t af[4][4], bf[8][2];
            #pragma unroll
            for (int mt = 0; mt < 4; mt++) {
                af[mt][0] = f2tf(As[cur][mrow + mt*16    ][kb  ]);
                af[mt][1] = f2tf(As[cur][mrow + mt*16 + 8][kb  ]);
                af[mt][2] = f2tf(As[cur][mrow + mt*16    ][kb+4]);
                af[mt][3] = f2tf(As[cur][mrow + mt*16 + 8][kb+4]);
            }
            #pragma unroll
            for (int nt = 0; nt < 8; nt++) {
                bf[nt][0] = f2tf(Ws[cur][nrow + nt*8][kb  ]);
                bf[nt][1] = f2tf(Ws[cur][nrow + nt*8][kb+4]);
            }
            #pragma unroll
            for (int mt = 0; mt < 4; mt++)
                #pragma unroll
                for (int nt = 0; nt < 8; nt++)
                    mma_tf32(acc[mt][nt], af[mt], bf[nt]);
        }
        __syncthreads();
    }

    // epilogue
    const int cn = bn + wn*64;
    float bv[8][2];
    #pragma unroll
    for (int nt = 0; nt < 8; nt++) {
        int c = cn + nt*8 + 2*(lane & 3);
        bv[nt][0] = bias[c];
        bv[nt][1] = bias[c+1];
    }
    #pragma unroll
    for (int mt = 0; mt < 4; mt++) {
        const int r0 = bm + wm*64 + mt*16 + (lane >> 2);
        #pragma unroll
        for (int half = 0; half < 2; half++) {
            const int r = r0 + half*8;
            if (r < M) {
                #pragma unroll
                for (int nt = 0; nt < 8; nt++) {
                    float x0 = acc[mt][nt][half*2+0] + bv[nt][0];
                    float x1 = acc[mt][nt][half*2+1] + bv[nt][1];
                    if (ACT) { x0 = gelu_t(x0); x1 = gelu_t(x1); }
                    float2 v = make_float2(x0, x1);
                    *(float2*)&C[(size_t)r*N + cn + nt*8 + 2*(lane & 3)] = v;
                }
            }
        }
    }
}

// ---------------------------------------------------------------------------
// out[row] = hid[row] + a*(x-mean)/(std(ddof=1)+eps) + b     (x = ffn[row])
// ---------------------------------------------------------------------------
__global__ void __launch_bounds__(128) ln_res_kernel(
    const float* __restrict__ hid, const float* __restrict__ ffn,
    const float* __restrict__ ga,  const float* __restrict__ gb,
    float* __restrict__ out)
{
    const int row = blockIdx.x;
    const int tid = threadIdx.x;
    float4 xv = ((const float4*)(ffn + (size_t)row*D_))[tid];
    float s = xv.x + xv.y + xv.z + xv.w;
    float q = xv.x*xv.x + xv.y*xv.y + xv.z*xv.z + xv.w*xv.w;
    #pragma unroll
    for (int o = 16; o > 0; o >>= 1) {
        s += __shfl_xor_sync(0xffffffffu, s, o);
        q += __shfl_xor_sync(0xffffffffu, q, o);
    }
    __shared__ float ss[4], sq[4];
    if ((tid & 31) == 0) { ss[tid>>5] = s; sq[tid>>5] = q; }
    __syncthreads();
    float S = ss[0]+ss[1]+ss[2]+ss[3];
    float Q = sq[0]+sq[1]+sq[2]+sq[3];
    float mean = S * (1.f/D_);
    float var  = (Q - (float)D_*mean*mean) * (1.f/(D_-1));
    var = fmaxf(var, 0.f);
    float inv = 1.f / (sqrtf(var) + 1e-6f);

    float4 hv = ((const float4*)(hid + (size_t)row*D_))[tid];
    float4 av = ((const float4*)ga)[tid];
    float4 bv = ((const float4*)gb)[tid];
    float4 o4;
    o4.x = hv.x + av.x*(xv.x-mean)*inv + bv.x;
    o4.y = hv.y + av.y*(xv.y-mean)*inv + bv.y;
    o4.z = hv.z + av.z*(xv.z-mean)*inv + bv.z;
    o4.w = hv.w + av.w*(xv.w-mean)*inv + bv.w;
    ((float4*)(out + (size_t)row*D_))[tid] = o4;
}

// ---------------------------------------------------------------------------
extern "C" void kernel_launch(void* const* d_in, const int* in_sizes, int n_in,
                              void* d_out, int out_size)
{
    const float* img    = (const float*)d_in[0];
    const float* title  = (const float*)d_in[1];
    const int*   mask   = (const int*)  d_in[2];
    const float* s_img  = (const float*)d_in[3];
    const float* s_tit  = (const float*)d_in[4];
    const float* w_proj = (const float*)d_in[5];
    const float* b_proj = (const float*)d_in[6];
    const float* w1i    = (const float*)d_in[7];
    const float* b1i    = (const float*)d_in[8];
    const float* w2i    = (const float*)d_in[9];
    const float* b2i    = (const float*)d_in[10];
    const float* w1t    = (const float*)d_in[11];
    const float* b1t    = (const float*)d_in[12];
    const float* w2t    = (const float*)d_in[13];
    const float* b2t    = (const float*)d_in[14];
    const float* lai    = (const float*)d_in[15];
    const float* lbi    = (const float*)d_in[16];
    const float* lat    = (const float*)d_in[17];
    const float* lbt    = (const float*)d_in[18];
    float* out = (float*)d_out;

    float *attn, *hid, *ffh, *ffo;
    cudaGetSymbolAddress((void**)&attn, g_attn);
    cudaGetSymbolAddress((void**)&hid,  g_hid);
    cudaGetSymbolAddress((void**)&ffh,  g_ffh);
    cudaGetSymbolAddress((void**)&ffo,  g_ffo);

    attn_kernel<<<B_*L_*H_, 256>>>(img, title, mask, s_img, s_tit, attn);

    // proj over all 55200 rows (grid.x = N blocks for A-tile L2 reuse)
    dim3 gP(D_/128, (ROWS_ALL+127)/128);
    gemm_tc<0><<<gP, 128>>>(attn, w_proj, b_proj, hid, ROWS_ALL, D_, D_);

    // img FFN + LN+residual
    dim3 g1i(DFF_/128, (ROWS_IMG+127)/128);
    gemm_tc<1><<<g1i, 128>>>(hid, w1i, b1i, ffh, ROWS_IMG, DFF_, D_);
    dim3 g2i(D_/128, (ROWS_IMG+127)/128);
    gemm_tc<0><<<g2i, 128>>>(ffh, w2i, b2i, ffo, ROWS_IMG, D_, DFF_);
    ln_res_kernel<<<ROWS_IMG, 128>>>(hid, ffo, lai, lbi, out);

    // tit FFN + LN+residual
    const float* hidT = hid + (size_t)ROWS_IMG*D_;
    dim3 g1t(DFF_/128, (ROWS_TIT+127)/128);
    gemm_tc<1><<<g1t, 128>>>(hidT, w1t, b1t, ffh, ROWS_TIT, DFF_, D_);
    dim3 g2t(D_/128, (ROWS_TIT+127)/128);
    gemm_tc<0><<<g2t, 128>>>(ffh, w2t, b2t, ffo, ROWS_TIT, D_, DFF_);
    ln_res_kernel<<<ROWS_TIT, 128>>>(hidT, ffo, lat, lbt, out + (size_t)ROWS_IMG*D_);
}

// round 3
// speedup vs baseline: 2.4613x; 1.2559x over previous
#include <cuda_runtime.h>
#include <math.h>
#include <stdint.h>

#define B_   16
#define L_   50
#define P_   49
#define T_   20
#define D_   512
#define H_   8
#define DH_  64
#define DFF_ 2048

#define ROWS_IMG (B_*L_*T_)            // 16000
#define ROWS_TIT (B_*L_*P_)            // 39200
#define ROWS_ALL (ROWS_IMG+ROWS_TIT)   // 55200

// ---------------------------------------------------------------------------
// Scratch (device globals: allocation-free, graph-capturable)
// ---------------------------------------------------------------------------
__device__ float g_attn[(size_t)ROWS_ALL * D_];
__device__ float g_hid [(size_t)ROWS_ALL * D_];
__device__ float g_ffh [(size_t)ROWS_TIT * DFF_];
__device__ float g_ffo [(size_t)ROWS_TIT * D_];

// ---------------------------------------------------------------------------
// Fused attention: one CTA per (b*l, h)
// ---------------------------------------------------------------------------
__global__ void __launch_bounds__(256) attn_kernel(
    const float* __restrict__ img,
    const float* __restrict__ title,
    const int*   __restrict__ mask,
    const float* __restrict__ scale_img,
    const float* __restrict__ scale_title,
    float*       __restrict__ attn_cat)
{
    const int h   = blockIdx.x & (H_-1);
    const int bl  = blockIdx.x >> 3;
    const int tid = threadIdx.x;

    __shared__ float im[P_][DH_+1];
    __shared__ float ti[T_][DH_+1];
    __shared__ float raw[P_][T_];
    __shared__ float pim[P_][T_];
    __shared__ float pti[T_][P_+3];
    __shared__ float s_si[P_];
    __shared__ float s_st[T_];
    __shared__ int   mk[T_];

    const float* ib = img   + (size_t)bl * (P_*D_) + h*DH_;
    for (int idx = tid; idx < P_*DH_; idx += 256) {
        int p = idx >> 6, d = idx & 63;
        im[p][d] = ib[p*D_ + d];
    }
    const float* tb = title + (size_t)bl * (T_*D_) + h*DH_;
    for (int idx = tid; idx < T_*DH_; idx += 256) {
        int t = idx >> 6, d = idx & 63;
        ti[t][d] = tb[t*D_ + d];
    }
    if (tid < T_) { mk[tid] = mask[bl*T_ + tid]; s_st[tid] = scale_title[h*T_ + tid]; }
    if (tid < P_) s_si[tid] = scale_img[h*P_ + tid];
    __syncthreads();

    for (int idx = tid; idx < P_*T_; idx += 256) {
        int p = idx / T_, t = idx % T_;
        float s = 0.f;
        #pragma unroll 16
        for (int d = 0; d < DH_; d++) s += im[p][d] * ti[t][d];
        raw[p][t] = s * 0.125f;
    }
    __syncthreads();

    if (tid < P_) {
        const int p = tid;
        const float sc = s_si[p];
        float v[T_];
        float mx = -3.4e38f;
        #pragma unroll
        for (int t = 0; t < T_; t++) {
            float x = mk[t] ? raw[p][t]*sc : -1e9f;
            v[t] = x;
            mx = fmaxf(mx, x);
        }
        float s = 0.f;
        #pragma unroll
        for (int t = 0; t < T_; t++) { float e = expf(v[t]-mx); v[t]=e; s+=e; }
        float inv = 1.f/s;
        #pragma unroll
        for (int t = 0; t < T_; t++) pim[p][t] = v[t]*inv;
    }
    if (tid >= 64 && tid < 64+T_) {
        const int t = tid - 64;
        const float sc = s_st[t];
        const bool valid = (mk[t] != 0);
        float mx = -3.4e38f;
        for (int p = 0; p < P_; p++) {
            float x = valid ? raw[p][t]*sc : -1e9f;
            pti[t][p] = x;
            mx = fmaxf(mx, x);
        }
        float s = 0.f;
        for (int p = 0; p < P_; p++) { float e = expf(pti[t][p]-mx); pti[t][p]=e; s+=e; }
        float inv = 1.f/s;
        for (int p = 0; p < P_; p++) pti[t][p] *= inv;
    }
    __syncthreads();

    for (int idx = tid; idx < P_*DH_; idx += 256) {
        int p = idx >> 6, d = idx & 63;
        float s = 0.f;
        #pragma unroll
        for (int t = 0; t < T_; t++) s += pim[p][t]*ti[t][d];
        attn_cat[(size_t)(ROWS_IMG + bl*P_ + p)*D_ + h*DH_ + d] = s;
    }
    for (int idx = tid; idx < T_*DH_; idx += 256) {
        int t = idx >> 6, d = idx & 63;
        float s = 0.f;
        #pragma unroll 7
        for (int p = 0; p < P_; p++) s += pti[t][p]*im[p][d];
        attn_cat[(size_t)(bl*T_ + t)*D_ + h*DH_ + d] = s;
    }
}

// ---------------------------------------------------------------------------
// TF32 tensor-core GEMM: C[M,N] = A[M,K]*W[N,K]^T + bias (opt. tanh-GELU)
// BM=BN=128, BK=16, 256 thr / 8 warps x (64x32 warp tile), 3-stage cp.async
// ---------------------------------------------------------------------------
__device__ __forceinline__ float gelu_t(float x) {
    float x3 = x*x*x;
    return 0.5f*x*(1.f + tanhf(0.7978845608028654f*(x + 0.044715f*x3)));
}

__device__ __forceinline__ uint32_t f2tf(float x) {
    uint32_t u;
    asm("cvt.rna.tf32.f32 %0, %1;" : "=r"(u) : "f"(x));
    return u;
}

__device__ __forceinline__ void mma_tf32(float* d, const uint32_t* a, const uint32_t* b) {
    asm volatile(
        "mma.sync.aligned.m16n8k8.row.col.f32.tf32.tf32.f32 "
        "{%0,%1,%2,%3}, {%4,%5,%6,%7}, {%8,%9}, {%0,%1,%2,%3};"
        : "+f"(d[0]), "+f"(d[1]), "+f"(d[2]), "+f"(d[3])
        : "r"(a[0]), "r"(a[1]), "r"(a[2]), "r"(a[3]), "r"(b[0]), "r"(b[1]));
}

__device__ __forceinline__ void cp16(void* smem_dst, const void* gsrc) {
    uint32_t d = (uint32_t)__cvta_generic_to_shared(smem_dst);
    asm volatile("cp.async.cg.shared.global [%0], [%1], 16;" :: "r"(d), "l"(gsrc));
}

#define SPITCH 20
#define STAGES 3

template<int ACT>
__global__ void __launch_bounds__(256, 2) gemm_tc(
    const float* __restrict__ A, const float* __restrict__ W,
    const float* __restrict__ bias, float* __restrict__ C,
    int M, int N, int K)
{
    __shared__ float As[STAGES][128][SPITCH];
    __shared__ float Ws[STAGES][128][SPITCH];

    const int tid  = threadIdx.x;
    const int lane = tid & 31;
    const int warp = tid >> 5;
    const int wm   = warp >> 2;     // 0..1  (64 rows)
    const int wn   = warp & 3;      // 0..3  (32 cols)

    const int bn = blockIdx.x * 128;
    const int bm = blockIdx.y * 128;

    // staging: thread owns row tid>>1, cols (tid&1)*8 .. +8
    const int srow = tid >> 1;
    const int scol = (tid & 1) * 8;
    const int  arow = bm + srow;
    const bool aok  = arow < M;
    const float* Ap = A + (size_t)arow * K + scol;
    const float* Wp = W + (size_t)(bn + srow) * K + scol;

    if (!aok) {
        #pragma unroll
        for (int s = 0; s < STAGES; s++)
            #pragma unroll
            for (int j = 0; j < 8; j++)
                As[s][srow][scol + j] = 0.f;
    }

    float acc[4][4][4];
    #pragma unroll
    for (int mt = 0; mt < 4; mt++)
        #pragma unroll
        for (int nt = 0; nt < 4; nt++)
            #pragma unroll
            for (int r = 0; r < 4; r++) acc[mt][nt][r] = 0.f;

    const int KT = K >> 4;

    // prologue: stage 0 and 1
    #pragma unroll
    for (int s = 0; s < 2; s++) {
        const int ko = s << 4;
        if (aok) { cp16(&As[s][srow][scol], Ap + ko); cp16(&As[s][srow][scol+4], Ap + ko + 4); }
        cp16(&Ws[s][srow][scol], Wp + ko); cp16(&Ws[s][srow][scol+4], Wp + ko + 4);
        asm volatile("cp.async.commit_group;");
    }

    const int mrow = wm*64 + (lane >> 2);
    const int nrow = wn*32 + (lane >> 2);

    for (int kt = 0; kt < KT; kt++) {
        const int cur = kt % STAGES;
        asm volatile("cp.async.wait_group 1;");
        __syncthreads();

        if (kt + 2 < KT) {
            const int nb = (kt + 2) % STAGES;
            const int ko = (kt + 2) << 4;
            if (aok) { cp16(&As[nb][srow][scol], Ap + ko); cp16(&As[nb][srow][scol+4], Ap + ko + 4); }
            cp16(&Ws[nb][srow][scol], Wp + ko); cp16(&Ws[nb][srow][scol+4], Wp + ko + 4);
            asm volatile("cp.async.commit_group;");
        }

        #pragma unroll
        for (int ks = 0; ks < 16; ks += 8) {
            const int kb = ks + (lane & 3);
            uint32_t af[4][4], bf[4][2];
            #pragma unroll
            for (int mt = 0; mt < 4; mt++) {
                af[mt][0] = f2tf(As[cur][mrow + mt*16    ][kb  ]);
                af[mt][1] = f2tf(As[cur][mrow + mt*16 + 8][kb  ]);
                af[mt][2] = f2tf(As[cur][mrow + mt*16    ][kb+4]);
                af[mt][3] = f2tf(As[cur][mrow + mt*16 + 8][kb+4]);
            }
            #pragma unroll
            for (int nt = 0; nt < 4; nt++) {
                bf[nt][0] = f2tf(Ws[cur][nrow + nt*8][kb  ]);
                bf[nt][1] = f2tf(Ws[cur][nrow + nt*8][kb+4]);
            }
            #pragma unroll
            for (int mt = 0; mt < 4; mt++)
                #pragma unroll
                for (int nt = 0; nt < 4; nt++)
                    mma_tf32(acc[mt][nt], af[mt], bf[nt]);
        }
        __syncthreads();
    }

    // epilogue
    const int cn = bn + wn*32;
    float bv[4][2];
    #pragma unroll
    for (int nt = 0; nt < 4; nt++) {
        int c = cn + nt*8 + 2*(lane & 3);
        bv[nt][0] = bias[c];
        bv[nt][1] = bias[c+1];
    }
    #pragma unroll
    for (int mt = 0; mt < 4; mt++) {
        const int r0 = bm + wm*64 + mt*16 + (lane >> 2);
        #pragma unroll
        for (int half = 0; half < 2; half++) {
            const int r = r0 + half*8;
            if (r < M) {
                #pragma unroll
                for (int nt = 0; nt < 4; nt++) {
                    float x0 = acc[mt][nt][half*2+0] + bv[nt][0];
                    float x1 = acc[mt][nt][half*2+1] + bv[nt][1];
                    if (ACT) { x0 = gelu_t(x0); x1 = gelu_t(x1); }
                    float2 v = make_float2(x0, x1);
                    *(float2*)&C[(size_t)r*N + cn + nt*8 + 2*(lane & 3)] = v;
                }
            }
        }
    }
}

// ---------------------------------------------------------------------------
// out[row] = hid[row] + a*(x-mean)/(std(ddof=1)+eps) + b     (x = ffn[row])
// ---------------------------------------------------------------------------
__global__ void __launch_bounds__(128) ln_res_kernel(
    const float* __restrict__ hid, const float* __restrict__ ffn,
    const float* __restrict__ ga,  const float* __restrict__ gb,
    float* __restrict__ out)
{
    const int row = blockIdx.x;
    const int tid = threadIdx.x;
    float4 xv = ((const float4*)(ffn + (size_t)row*D_))[tid];
    float s = xv.x + xv.y + xv.z + xv.w;
    float q = xv.x*xv.x + xv.y*xv.y + xv.z*xv.z + xv.w*xv.w;
    #pragma unroll
    for (int o = 16; o > 0; o >>= 1) {
        s += __shfl_xor_sync(0xffffffffu, s, o);
        q += __shfl_xor_sync(0xffffffffu, q, o);
    }
    __shared__ float ss[4], sq[4];
    if ((tid & 31) == 0) { ss[tid>>5] = s; sq[tid>>5] = q; }
    __syncthreads();
    float S = ss[0]+ss[1]+ss[2]+ss[3];
    float Q = sq[0]+sq[1]+sq[2]+sq[3];
    float mean = S * (1.f/D_);
    float var  = (Q - (float)D_*mean*mean) * (1.f/(D_-1));
    var = fmaxf(var, 0.f);
    float inv = 1.f / (sqrtf(var) + 1e-6f);

    float4 hv = ((const float4*)(hid + (size_t)row*D_))[tid];
    float4 av = ((const float4*)ga)[tid];
    float4 bv = ((const float4*)gb)[tid];
    float4 o4;
    o4.x = hv.x + av.x*(xv.x-mean)*inv + bv.x;
    o4.y = hv.y + av.y*(xv.y-mean)*inv + bv.y;
    o4.z = hv.z + av.z*(xv.z-mean)*inv + bv.z;
    o4.w = hv.w + av.w*(xv.w-mean)*inv + bv.w;
    ((float4*)(out + (size_t)row*D_))[tid] = o4;
}

// ---------------------------------------------------------------------------
extern "C" void kernel_launch(void* const* d_in, const int* in_sizes, int n_in,
                              void* d_out, int out_size)
{
    const float* img    = (const float*)d_in[0];
    const float* title  = (const float*)d_in[1];
    const int*   mask   = (const int*)  d_in[2];
    const float* s_img  = (const float*)d_in[3];
    const float* s_tit  = (const float*)d_in[4];
    const float* w_proj = (const float*)d_in[5];
    const float* b_proj = (const float*)d_in[6];
    const float* w1i    = (const float*)d_in[7];
    const float* b1i    = (const float*)d_in[8];
    const float* w2i    = (const float*)d_in[9];
    const float* b2i    = (const float*)d_in[10];
    const float* w1t    = (const float*)d_in[11];
    const float* b1t    = (const float*)d_in[12];
    const float* w2t    = (const float*)d_in[13];
    const float* b2t    = (const float*)d_in[14];
    const float* lai    = (const float*)d_in[15];
    const float* lbi    = (const float*)d_in[16];
    const float* lat    = (const float*)d_in[17];
    const float* lbt    = (const float*)d_in[18];
    float* out = (float*)d_out;

    float *attn, *hid, *ffh, *ffo;
    cudaGetSymbolAddress((void**)&attn, g_attn);
    cudaGetSymbolAddress((void**)&hid,  g_hid);
    cudaGetSymbolAddress((void**)&ffh,  g_ffh);
    cudaGetSymbolAddress((void**)&ffo,  g_ffo);

    attn_kernel<<<B_*L_*H_, 256>>>(img, title, mask, s_img, s_tit, attn);

    dim3 gP(D_/128, (ROWS_ALL+127)/128);
    gemm_tc<0><<<gP, 256>>>(attn, w_proj, b_proj, hid, ROWS_ALL, D_, D_);

    dim3 g1i(DFF_/128, (ROWS_IMG+127)/128);
    gemm_tc<1><<<g1i, 256>>>(hid, w1i, b1i, ffh, ROWS_IMG, DFF_, D_);
    dim3 g2i(D_/128, (ROWS_IMG+127)/128);
    gemm_tc<0><<<g2i, 256>>>(ffh, w2i, b2i, ffo, ROWS_IMG, D_, DFF_);
    ln_res_kernel<<<ROWS_IMG, 128>>>(hid, ffo, lai, lbi, out);

    const float* hidT = hid + (size_t)ROWS_IMG*D_;
    dim3 g1t(DFF_/128, (ROWS_TIT+127)/128);
    gemm_tc<1><<<g1t, 256>>>(hidT, w1t, b1t, ffh, ROWS_TIT, DFF_, D_);
    dim3 g2t(D_/128, (ROWS_TIT+127)/128);
    gemm_tc<0><<<g2t, 256>>>(ffh, w2t, b2t, ffo, ROWS_TIT, D_, DFF_);
    ln_res_kernel<<<ROWS_TIT, 128>>>(hidT, ffo, lat, lbt, out + (size_t)ROWS_IMG*D_);
}

// round 5
// speedup vs baseline: 2.7281x; 1.1084x over previous
#include <cuda_runtime.h>
#include <math.h>
#include <stdint.h>

#define B_   16
#define L_   50
#define P_   49
#define T_   20
#define D_   512
#define H_   8
#define DH_  64
#define DFF_ 2048

#define ROWS_IMG (B_*L_*T_)            // 16000
#define ROWS_TIT (B_*L_*P_)            // 39200
#define ROWS_ALL (ROWS_IMG+ROWS_TIT)   // 55200

// ---------------------------------------------------------------------------
// Scratch (device globals)
// ---------------------------------------------------------------------------
__device__ float g_attn[(size_t)ROWS_ALL * D_];    // rounded tf32 (GEMM-only)
__device__ float g_hid [(size_t)ROWS_ALL * D_];    // fp32 (residual)
__device__ float g_hidt[(size_t)ROWS_ALL * D_];    // rounded tf32 (FFN1 input)
__device__ float g_ffh [(size_t)ROWS_TIT * DFF_];  // rounded tf32 (FFN2 input)
__device__ float g_ffo [(size_t)ROWS_TIT * D_];    // fp32
__device__ float g_wpt [D_*D_];                    // rounded weights
__device__ float g_w1it[DFF_*D_];
__device__ float g_w2it[D_*DFF_];
__device__ float g_w1tt[DFF_*D_];
__device__ float g_w2tt[D_*DFF_];

__device__ __forceinline__ uint32_t f2tf(float x) {
    uint32_t u;
    asm("cvt.rna.tf32.f32 %0, %1;" : "=r"(u) : "f"(x));
    return u;
}
__device__ __forceinline__ float rnd_tf(float x) { return __uint_as_float(f2tf(x)); }

// ---------------------------------------------------------------------------
// Round fp32 -> tf32-representable fp32 (vectorized, grid-stride)
// ---------------------------------------------------------------------------
__global__ void __launch_bounds__(256) round_tf32_kernel(
    const float* __restrict__ in, float* __restrict__ out, int n4)
{
    for (int i = blockIdx.x*blockDim.x + threadIdx.x; i < n4; i += gridDim.x*blockDim.x) {
        float4 v = ((const float4*)in)[i];
        v.x = rnd_tf(v.x); v.y = rnd_tf(v.y); v.z = rnd_tf(v.z); v.w = rnd_tf(v.w);
        ((float4*)out)[i] = v;
    }
}

// ---------------------------------------------------------------------------
// Fused attention: one CTA per (b*l, h); outputs tf32-rounded
// ---------------------------------------------------------------------------
__global__ void __launch_bounds__(256) attn_kernel(
    const float* __restrict__ img,
    const float* __restrict__ title,
    const int*   __restrict__ mask,
    const float* __restrict__ scale_img,
    const float* __restrict__ scale_title,
    float*       __restrict__ attn_cat)
{
    const int h   = blockIdx.x & (H_-1);
    const int bl  = blockIdx.x >> 3;
    const int tid = threadIdx.x;

    __shared__ float im[P_][DH_+1];
    __shared__ float ti[T_][DH_+1];
    __shared__ float raw[P_][T_];
    __shared__ float pim[P_][T_];
    __shared__ float pti[T_][P_+3];
    __shared__ float s_si[P_];
    __shared__ float s_st[T_];
    __shared__ int   mk[T_];

    const float* ib = img   + (size_t)bl * (P_*D_) + h*DH_;
    for (int idx = tid; idx < P_*DH_; idx += 256) {
        int p = idx >> 6, d = idx & 63;
        im[p][d] = ib[p*D_ + d];
    }
    const float* tb = title + (size_t)bl * (T_*D_) + h*DH_;
    for (int idx = tid; idx < T_*DH_; idx += 256) {
        int t = idx >> 6, d = idx & 63;
        ti[t][d] = tb[t*D_ + d];
    }
    if (tid < T_) { mk[tid] = mask[bl*T_ + tid]; s_st[tid] = scale_title[h*T_ + tid]; }
    if (tid < P_) s_si[tid] = scale_img[h*P_ + tid];
    __syncthreads();

    for (int idx = tid; idx < P_*T_; idx += 256) {
        int p = idx / T_, t = idx % T_;
        float s = 0.f;
        #pragma unroll 16
        for (int d = 0; d < DH_; d++) s += im[p][d] * ti[t][d];
        raw[p][t] = s * 0.125f;
    }
    __syncthreads();

    if (tid < P_) {
        const int p = tid;
        const float sc = s_si[p];
        float v[T_];
        float mx = -3.4e38f;
        #pragma unroll
        for (int t = 0; t < T_; t++) {
            float x = mk[t] ? raw[p][t]*sc : -1e9f;
            v[t] = x;
            mx = fmaxf(mx, x);
        }
        float s = 0.f;
        #pragma unroll
        for (int t = 0; t < T_; t++) { float e = expf(v[t]-mx); v[t]=e; s+=e; }
        float inv = 1.f/s;
        #pragma unroll
        for (int t = 0; t < T_; t++) pim[p][t] = v[t]*inv;
    }
    if (tid >= 64 && tid < 64+T_) {
        const int t = tid - 64;
        const float sc = s_st[t];
        const bool valid = (mk[t] != 0);
        float mx = -3.4e38f;
        for (int p = 0; p < P_; p++) {
            float x = valid ? raw[p][t]*sc : -1e9f;
            pti[t][p] = x;
            mx = fmaxf(mx, x);
        }
        float s = 0.f;
        for (int p = 0; p < P_; p++) { float e = expf(pti[t][p]-mx); pti[t][p]=e; s+=e; }
        float inv = 1.f/s;
        for (int p = 0; p < P_; p++) pti[t][p] *= inv;
    }
    __syncthreads();

    for (int idx = tid; idx < P_*DH_; idx += 256) {
        int p = idx >> 6, d = idx & 63;
        float s = 0.f;
        #pragma unroll
        for (int t = 0; t < T_; t++) s += pim[p][t]*ti[t][d];
        attn_cat[(size_t)(ROWS_IMG + bl*P_ + p)*D_ + h*DH_ + d] = rnd_tf(s);
    }
    for (int idx = tid; idx < T_*DH_; idx += 256) {
        int t = idx >> 6, d = idx & 63;
        float s = 0.f;
        #pragma unroll 7
        for (int p = 0; p < P_; p++) s += pti[t][p]*im[p][d];
        attn_cat[(size_t)(bl*T_ + t)*D_ + h*DH_ + d] = rnd_tf(s);
    }
}

// ---------------------------------------------------------------------------
// TF32 tensor-core GEMM (inputs pre-rounded): C = A*W^T + bias
// BM=BN=128, BK=16, 256 thr / 8 warps x (64x32 tile), 3-stage cp.async,
// ldmatrix fragment loads (no CVT in mainloop)
// MODE: 0 = fp32 out, 1 = tf32-rounded out, 2 = fp32 C + rounded C2
// ---------------------------------------------------------------------------
__device__ __forceinline__ float gelu_t(float x) {
    float x3 = x*x*x;
    return 0.5f*x*(1.f + tanhf(0.7978845608028654f*(x + 0.044715f*x3)));
}

__device__ __forceinline__ void mma_tf32(float* d, const uint32_t* a, const uint32_t* b) {
    asm volatile(
        "mma.sync.aligned.m16n8k8.row.col.f32.tf32.tf32.f32 "
        "{%0,%1,%2,%3}, {%4,%5,%6,%7}, {%8,%9}, {%0,%1,%2,%3};"
        : "+f"(d[0]), "+f"(d[1]), "+f"(d[2]), "+f"(d[3])
        : "r"(a[0]), "r"(a[1]), "r"(a[2]), "r"(a[3]), "r"(b[0]), "r"(b[1]));
}

__device__ __forceinline__ void cp16(void* smem_dst, const void* gsrc) {
    uint32_t d = (uint32_t)__cvta_generic_to_shared(smem_dst);
    asm volatile("cp.async.cg.shared.global [%0], [%1], 16;" :: "r"(d), "l"(gsrc));
}

__device__ __forceinline__ void ldsm4(uint32_t* r, uint32_t addr) {
    asm volatile("ldmatrix.sync.aligned.m8n8.x4.shared.b16 {%0,%1,%2,%3}, [%4];"
        : "=r"(r[0]), "=r"(r[1]), "=r"(r[2]), "=r"(r[3]) : "r"(addr));
}

#define SPITCH 20
#define STAGES 3

template<int ACT, int MODE>
__global__ void __launch_bounds__(256, 2) gemm_tc(
    const float* __restrict__ A, const float* __restrict__ W,
    const float* __restrict__ bias, float* __restrict__ C,
    float* __restrict__ C2, int M, int N, int K)
{
    __shared__ float As[STAGES][128][SPITCH];
    __shared__ float Ws[STAGES][128][SPITCH];

    const int tid  = threadIdx.x;
    const int lane = tid & 31;
    const int warp = tid >> 5;
    const int wm   = warp >> 2;     // 0..1
    const int wn   = warp & 3;      // 0..3

    const int bn = blockIdx.x * 128;
    const int bm = blockIdx.y * 128;

    const int srow = tid >> 1;
    const int scol = (tid & 1) * 8;
    const int  arow = bm + srow;
    const bool aok  = arow < M;
    const float* Ap = A + (size_t)arow * K + scol;
    const float* Wp = W + (size_t)(bn + srow) * K + scol;

    if (!aok) {
        #pragma unroll
        for (int s = 0; s < STAGES; s++)
            #pragma unroll
            for (int j = 0; j < 8; j++)
                As[s][srow][scol + j] = 0.f;
    }

    float acc[4][4][4];
    #pragma unroll
    for (int mt = 0; mt < 4; mt++)
        #pragma unroll
        for (int nt = 0; nt < 4; nt++)
            #pragma unroll
            for (int r = 0; r < 4; r++) acc[mt][nt][r] = 0.f;

    const int KT = K >> 4;

    // prologue: stages 0..1
    #pragma unroll
    for (int s = 0; s < 2; s++) {
        const int ko = s << 4;
        if (aok) { cp16(&As[s][srow][scol], Ap + ko); cp16(&As[s][srow][scol+4], Ap + ko + 4); }
        cp16(&Ws[s][srow][scol], Wp + ko); cp16(&Ws[s][srow][scol+4], Wp + ko + 4);
        asm volatile("cp.async.commit_group;");
    }

    // ldmatrix lane->address maps
    const int a_row = wm*64 + (lane & 15);
    const int a_col = (lane >> 4) << 2;                    // 0 or 4
    const int b_row = wn*32 + (lane & 7) + ((lane & 16) >> 1);
    const int b_col = (lane & 8) >> 1;                     // 0 or 4
    uint32_t a_base[STAGES], b_base[STAGES];
    #pragma unroll
    for (int s = 0; s < STAGES; s++) {
        a_base[s] = (uint32_t)__cvta_generic_to_shared(&As[s][a_row][a_col]);
        b_base[s] = (uint32_t)__cvta_generic_to_shared(&Ws[s][b_row][b_col]);
    }

    for (int kt = 0; kt < KT; kt++) {
        const int cur = kt % STAGES;
        asm volatile("cp.async.wait_group 1;");
        __syncthreads();

        if (kt + 2 < KT) {
            const int nb = (kt + 2) % STAGES;
            const int ko = (kt + 2) << 4;
            if (aok) { cp16(&As[nb][srow][scol], Ap + ko); cp16(&As[nb][srow][scol+4], Ap + ko + 4); }
            cp16(&Ws[nb][srow][scol], Wp + ko); cp16(&Ws[nb][srow][scol+4], Wp + ko + 4);
            asm volatile("cp.async.commit_group;");
        }

        #pragma unroll
        for (int ks = 0; ks < 16; ks += 8) {
            uint32_t af[4][4], bf[2][4];
            #pragma unroll
            for (int mt = 0; mt < 4; mt++)
                ldsm4(af[mt], a_base[cur] + (uint32_t)((ks + mt*16*SPITCH) * 4));
            #pragma unroll
            for (int pr = 0; pr < 2; pr++)
                ldsm4(bf[pr], b_base[cur] + (uint32_t)((ks + pr*16*SPITCH) * 4));
            #pragma unroll
            for (int mt = 0; mt < 4; mt++)
                #pragma unroll
                for (int nt = 0; nt < 4; nt++)
                    mma_tf32(acc[mt][nt], af[mt], &bf[nt>>1][(nt&1)*2]);
        }
        __syncthreads();
    }

    // epilogue
    const int cn = bn + wn*32;
    float bv[4][2];
    #pragma unroll
    for (int nt = 0; nt < 4; nt++) {
        int c = cn + nt*8 + 2*(lane & 3);
        bv[nt][0] = bias[c];
        bv[nt][1] = bias[c+1];
    }
    #pragma unroll
    for (int mt = 0; mt < 4; mt++) {
        const int r0 = bm + wm*64 + mt*16 + (lane >> 2);
        #pragma unroll
        for (int half = 0; half < 2; half++) {
            const int r = r0 + half*8;
            if (r < M) {
                #pragma unroll
                for (int nt = 0; nt < 4; nt++) {
                    float x0 = acc[mt][nt][half*2+0] + bv[nt][0];
                    float x1 = acc[mt][nt][half*2+1] + bv[nt][1];
                    if (ACT) { x0 = gelu_t(x0); x1 = gelu_t(x1); }
                    const size_t off = (size_t)r*N + cn + nt*8 + 2*(lane & 3);
                    if (MODE == 0) {
                        *(float2*)&C[off] = make_float2(x0, x1);
                    } else if (MODE == 1) {
                        *(float2*)&C[off] = make_float2(rnd_tf(x0), rnd_tf(x1));
                    } else {
                        *(float2*)&C[off]  = make_float2(x0, x1);
                        *(float2*)&C2[off] = make_float2(rnd_tf(x0), rnd_tf(x1));
                    }
                }
            }
        }
    }
}

// ---------------------------------------------------------------------------
// out[row] = hid[row] + a*(x-mean)/(std(ddof=1)+eps) + b
// ---------------------------------------------------------------------------
__global__ void __launch_bounds__(128) ln_res_kernel(
    const float* __restrict__ hid, const float* __restrict__ ffn,
    const float* __restrict__ ga,  const float* __restrict__ gb,
    float* __restrict__ out)
{
    const int row = blockIdx.x;
    const int tid = threadIdx.x;
    float4 xv = ((const float4*)(ffn + (size_t)row*D_))[tid];
    float s = xv.x + xv.y + xv.z + xv.w;
    float q = xv.x*xv.x + xv.y*xv.y + xv.z*xv.z + xv.w*xv.w;
    #pragma unroll
    for (int o = 16; o > 0; o >>= 1) {
        s += __shfl_xor_sync(0xffffffffu, s, o);
        q += __shfl_xor_sync(0xffffffffu, q, o);
    }
    __shared__ float ss[4], sq[4];
    if ((tid & 31) == 0) { ss[tid>>5] = s; sq[tid>>5] = q; }
    __syncthreads();
    float S = ss[0]+ss[1]+ss[2]+ss[3];
    float Q = sq[0]+sq[1]+sq[2]+sq[3];
    float mean = S * (1.f/D_);
    float var  = (Q - (float)D_*mean*mean) * (1.f/(D_-1));
    var = fmaxf(var, 0.f);
    float inv = 1.f / (sqrtf(var) + 1e-6f);

    float4 hv = ((const float4*)(hid + (size_t)row*D_))[tid];
    float4 av = ((const float4*)ga)[tid];
    float4 bv = ((const float4*)gb)[tid];
    float4 o4;
    o4.x = hv.x + av.x*(xv.x-mean)*inv + bv.x;
    o4.y = hv.y + av.y*(xv.y-mean)*inv + bv.y;
    o4.z = hv.z + av.z*(xv.z-mean)*inv + bv.z;
    o4.w = hv.w + av.w*(xv.w-mean)*inv + bv.w;
    ((float4*)(out + (size_t)row*D_))[tid] = o4;
}

// ---------------------------------------------------------------------------
extern "C" void kernel_launch(void* const* d_in, const int* in_sizes, int n_in,
                              void* d_out, int out_size)
{
    const float* img    = (const float*)d_in[0];
    const float* title  = (const float*)d_in[1];
    const int*   mask   = (const int*)  d_in[2];
    const float* s_img  = (const float*)d_in[3];
    const float* s_tit  = (const float*)d_in[4];
    const float* w_proj = (const float*)d_in[5];
    const float* b_proj = (const float*)d_in[6];
    const float* w1i    = (const float*)d_in[7];
    const float* b1i    = (const float*)d_in[8];
    const float* w2i    = (const float*)d_in[9];
    const float* b2i    = (const float*)d_in[10];
    const float* w1t    = (const float*)d_in[11];
    const float* b1t    = (const float*)d_in[12];
    const float* w2t    = (const float*)d_in[13];
    const float* b2t    = (const float*)d_in[14];
    const float* lai    = (const float*)d_in[15];
    const float* lbi    = (const float*)d_in[16];
    const float* lat    = (const float*)d_in[17];
    const float* lbt    = (const float*)d_in[18];
    float* out = (float*)d_out;

    float *attn, *hid, *hidt, *ffh, *ffo;
    float *wpt, *w1it, *w2it, *w1tt, *w2tt;
    cudaGetSymbolAddress((void**)&attn, g_attn);
    cudaGetSymbolAddress((void**)&hid,  g_hid);
    cudaGetSymbolAddress((void**)&hidt, g_hidt);
    cudaGetSymbolAddress((void**)&ffh,  g_ffh);
    cudaGetSymbolAddress((void**)&ffo,  g_ffo);
    cudaGetSymbolAddress((void**)&wpt,  g_wpt);
    cudaGetSymbolAddress((void**)&w1it, g_w1it);
    cudaGetSymbolAddress((void**)&w2it, g_w2it);
    cudaGetSymbolAddress((void**)&w1tt, g_w1tt);
    cudaGetSymbolAddress((void**)&w2tt, g_w2tt);

    // weight pre-rounding (~18MB total)
    round_tf32_kernel<<<256, 256>>>(w_proj, wpt, D_*D_/4);
    round_tf32_kernel<<<512, 256>>>(w1i, w1it, DFF_*D_/4);
    round_tf32_kernel<<<512, 256>>>(w2i, w2it, D_*DFF_/4);
    round_tf32_kernel<<<512, 256>>>(w1t, w1tt, DFF_*D_/4);
    round_tf32_kernel<<<512, 256>>>(w2t, w2tt, D_*DFF_/4);

    attn_kernel<<<B_*L_*H_, 256>>>(img, title, mask, s_img, s_tit, attn);

    dim3 gP(D_/128, (ROWS_ALL+127)/128);
    gemm_tc<0,2><<<gP, 256>>>(attn, wpt, b_proj, hid, hidt, ROWS_ALL, D_, D_);

    dim3 g1i(DFF_/128, (ROWS_IMG+127)/128);
    gemm_tc<1,1><<<g1i, 256>>>(hidt, w1it, b1i, ffh, (float*)0, ROWS_IMG, DFF_, D_);
    dim3 g2i(D_/128, (ROWS_IMG+127)/128);
    gemm_tc<0,0><<<g2i, 256>>>(ffh, w2it, b2i, ffo, (float*)0, ROWS_IMG, D_, DFF_);
    ln_res_kernel<<<ROWS_IMG, 128>>>(hid, ffo, lai, lbi, out);

    const float* hidtT = hidt + (size_t)ROWS_IMG*D_;
    dim3 g1t(DFF_/128, (ROWS_TIT+127)/128);
    gemm_tc<1,1><<<g1t, 256>>>(hidtT, w1tt, b1t, ffh, (float*)0, ROWS_TIT, DFF_, D_);
    dim3 g2t(D_/128, (ROWS_TIT+127)/128);
    gemm_tc<0,0><<<g2t, 256>>>(ffh, w2tt, b2t, ffo, (float*)0, ROWS_TIT, D_, DFF_);
    ln_res_kernel<<<ROWS_TIT, 128>>>(hid + (size_t)ROWS_IMG*D_, ffo, lat, lbt,
                                     out + (size_t)ROWS_IMG*D_);
}

// round 7
// speedup vs baseline: 4.5070x; 1.6521x over previous
#include <cuda_runtime.h>
#include <cuda_fp16.h>
#include <math.h>
#include <stdint.h>

#define B_   16
#define L_   50
#define P_   49
#define T_   20
#define D_   512
#define H_   8
#define DH_  64
#define DFF_ 2048

#define ROWS_IMG (B_*L_*T_)            // 16000
#define ROWS_TIT (B_*L_*P_)            // 39200
#define ROWS_ALL (ROWS_IMG+ROWS_TIT)   // 55200

// ---------------------------------------------------------------------------
// Scratch (device globals)
// ---------------------------------------------------------------------------
__device__ __half g_attn[(size_t)ROWS_ALL * D_];   // fp16 (proj GEMM input)
__device__ float  g_hid [(size_t)ROWS_ALL * D_];   // fp32 (residual)
__device__ __half g_hidh[(size_t)ROWS_ALL * D_];   // fp16 (FFN1 input)
__device__ __half g_ffh [(size_t)ROWS_TIT * DFF_]; // fp16 (FFN2 input)
__device__ float  g_ffo [(size_t)ROWS_TIT * D_];   // fp32
__device__ __half g_wph [D_*D_];                   // fp16 weights
__device__ __half g_w1ih[DFF_*D_];
__device__ __half g_w2ih[D_*DFF_];
__device__ __half g_w1th[DFF_*D_];
__device__ __half g_w2th[D_*DFF_];

// ---------------------------------------------------------------------------
// fp32 -> fp16 conversion (vectorized, grid-stride)
// ---------------------------------------------------------------------------
__global__ void __launch_bounds__(256) to_half_kernel(
    const float* __restrict__ in, __half* __restrict__ out, int n4)
{
    for (int i = blockIdx.x*blockDim.x + threadIdx.x; i < n4; i += gridDim.x*blockDim.x) {
        float4 v = ((const float4*)in)[i];
        __half2 h0 = __floats2half2_rn(v.x, v.y);
        __half2 h1 = __floats2half2_rn(v.z, v.w);
        ((__half2*)out)[2*i]   = h0;
        ((__half2*)out)[2*i+1] = h1;
    }
}

// ---------------------------------------------------------------------------
// Fused attention: one CTA per (b*l, h); outputs fp16
// ---------------------------------------------------------------------------
__global__ void __launch_bounds__(256) attn_kernel(
    const float* __restrict__ img,
    const float* __restrict__ title,
    const int*   __restrict__ mask,
    const float* __restrict__ scale_img,
    const float* __restrict__ scale_title,
    __half*      __restrict__ attn_cat)
{
    const int h   = blockIdx.x & (H_-1);
    const int bl  = blockIdx.x >> 3;
    const int tid = threadIdx.x;

    __shared__ float im[P_][DH_+1];
    __shared__ float ti[T_][DH_+1];
    __shared__ float raw[P_][T_];
    __shared__ float pim[P_][T_];
    __shared__ float pti[T_][P_+3];
    __shared__ float s_si[P_];
    __shared__ float s_st[T_];
    __shared__ int   mk[T_];

    const float* ib = img   + (size_t)bl * (P_*D_) + h*DH_;
    for (int idx = tid; idx < P_*DH_; idx += 256) {
        int p = idx >> 6, d = idx & 63;
        im[p][d] = ib[p*D_ + d];
    }
    const float* tb = title + (size_t)bl * (T_*D_) + h*DH_;
    for (int idx = tid; idx < T_*DH_; idx += 256) {
        int t = idx >> 6, d = idx & 63;
        ti[t][d] = tb[t*D_ + d];
    }
    if (tid < T_) { mk[tid] = mask[bl*T_ + tid]; s_st[tid] = scale_title[h*T_ + tid]; }
    if (tid < P_) s_si[tid] = scale_img[h*P_ + tid];
    __syncthreads();

    for (int idx = tid; idx < P_*T_; idx += 256) {
        int p = idx / T_, t = idx % T_;
        float s = 0.f;
        #pragma unroll 16
        for (int d = 0; d < DH_; d++) s += im[p][d] * ti[t][d];
        raw[p][t] = s * 0.125f;
    }
    __syncthreads();

    if (tid < P_) {
        const int p = tid;
        const float sc = s_si[p];
        float v[T_];
        float mx = -3.4e38f;
        #pragma unroll
        for (int t = 0; t < T_; t++) {
            float x = mk[t] ? raw[p][t]*sc : -1e9f;
            v[t] = x;
            mx = fmaxf(mx, x);
        }
        float s = 0.f;
        #pragma unroll
        for (int t = 0; t < T_; t++) { float e = expf(v[t]-mx); v[t]=e; s+=e; }
        float inv = 1.f/s;
        #pragma unroll
        for (int t = 0; t < T_; t++) pim[p][t] = v[t]*inv;
    }
    if (tid >= 64 && tid < 64+T_) {
        const int t = tid - 64;
        const float sc = s_st[t];
        const bool valid = (mk[t] != 0);
        float mx = -3.4e38f;
        for (int p = 0; p < P_; p++) {
            float x = valid ? raw[p][t]*sc : -1e9f;
            pti[t][p] = x;
            mx = fmaxf(mx, x);
        }
        float s = 0.f;
        for (int p = 0; p < P_; p++) { float e = expf(pti[t][p]-mx); pti[t][p]=e; s+=e; }
        float inv = 1.f/s;
        for (int p = 0; p < P_; p++) pti[t][p] *= inv;
    }
    __syncthreads();

    for (int idx = tid; idx < P_*DH_; idx += 256) {
        int p = idx >> 6, d = idx & 63;
        float s = 0.f;
        #pragma unroll
        for (int t = 0; t < T_; t++) s += pim[p][t]*ti[t][d];
        attn_cat[(size_t)(ROWS_IMG + bl*P_ + p)*D_ + h*DH_ + d] = __float2half_rn(s);
    }
    for (int idx = tid; idx < T_*DH_; idx += 256) {
        int t = idx >> 6, d = idx & 63;
        float s = 0.f;
        #pragma unroll 7
        for (int p = 0; p < P_; p++) s += pti[t][p]*im[p][d];
        attn_cat[(size_t)(bl*T_ + t)*D_ + h*DH_ + d] = __float2half_rn(s);
    }
}

// ---------------------------------------------------------------------------
// fp16 tensor-core GEMM: C = A[M,K]*W[N,K]^T + bias (fp32 accumulate)
// BM=BN=128, BK=32, 256 thr / 8 warps x (64x32 tile), 3-stage cp.async,
// ldmatrix fragment loads, mma.sync m16n8k16
// MODE: 0 = fp32 out C, 1 = fp16 out Ch, 2 = fp32 C + fp16 Ch
// ---------------------------------------------------------------------------
__device__ __forceinline__ float gelu_t(float x) {
    float x3 = x*x*x;
    return 0.5f*x*(1.f + tanhf(0.7978845608028654f*(x + 0.044715f*x3)));
}

__device__ __forceinline__ void mma_h(float* d, const uint32_t* a, const uint32_t* b) {
    asm volatile(
        "mma.sync.aligned.m16n8k16.row.col.f32.f16.f16.f32 "
        "{%0,%1,%2,%3}, {%4,%5,%6,%7}, {%8,%9}, {%0,%1,%2,%3};"
        : "+f"(d[0]), "+f"(d[1]), "+f"(d[2]), "+f"(d[3])
        : "r"(a[0]), "r"(a[1]), "r"(a[2]), "r"(a[3]), "r"(b[0]), "r"(b[1]));
}

__device__ __forceinline__ void cp16(void* smem_dst, const void* gsrc) {
    uint32_t d = (uint32_t)__cvta_generic_to_shared(smem_dst);
    asm volatile("cp.async.cg.shared.global [%0], [%1], 16;" :: "r"(d), "l"(gsrc));
}

__device__ __forceinline__ void ldsm4(uint32_t* r, uint32_t addr) {
    asm volatile("ldmatrix.sync.aligned.m8n8.x4.shared.b16 {%0,%1,%2,%3}, [%4];"
        : "=r"(r[0]), "=r"(r[1]), "=r"(r[2]), "=r"(r[3]) : "r"(addr));
}

#define HPITCH 40          // halves (80 bytes/row)
#define STAGES 3

template<int ACT, int MODE>
__global__ void __launch_bounds__(256, 2) gemm_h(
    const __half* __restrict__ A, const __half* __restrict__ W,
    const float* __restrict__ bias, float* __restrict__ C,
    __half* __restrict__ Ch, int M, int N, int K)
{
    __shared__ __half As[STAGES][128][HPITCH];
    __shared__ __half Ws[STAGES][128][HPITCH];

    const int tid  = threadIdx.x;
    const int lane = tid & 31;
    const int warp = tid >> 5;
    const int wm   = warp >> 2;     // 0..1
    const int wn   = warp & 3;      // 0..3

    const int bn = blockIdx.x * 128;
    const int bm = blockIdx.y * 128;

    // staging: thread -> row tid>>1, halves (tid&1)*16 .. +16  (2x cp16)
    const int srow = tid >> 1;
    const int scol = (tid & 1) * 16;
    const int  arow = bm + srow;
    const bool aok  = arow < M;
    const __half* Ap = A + (size_t)arow * K + scol;
    const __half* Wp = W + (size_t)(bn + srow) * K + scol;

    if (!aok) {
        #pragma unroll
        for (int s = 0; s < STAGES; s++)
            #pragma unroll
            for (int j = 0; j < 16; j++)
                As[s][srow][scol + j] = __float2half_rn(0.f);
    }

    float acc[4][4][4];
    #pragma unroll
    for (int mt = 0; mt < 4; mt++)
        #pragma unroll
        for (int nt = 0; nt < 4; nt++)
            #pragma unroll
            for (int r = 0; r < 4; r++) acc[mt][nt][r] = 0.f;

    const int KT = K >> 5;

    // prologue: stages 0..1
    #pragma unroll
    for (int s = 0; s < 2; s++) {
        const int ko = s << 5;
        if (aok) { cp16(&As[s][srow][scol], Ap + ko); cp16(&As[s][srow][scol+8], Ap + ko + 8); }
        cp16(&Ws[s][srow][scol], Wp + ko); cp16(&Ws[s][srow][scol+8], Wp + ko + 8);
        asm volatile("cp.async.commit_group;");
    }

    // ldmatrix lane->address maps
    // A (m16xk16): lanes0-7 -> rows m0-7 @k0, 8-15 -> m8-15 @k0, 16-23 -> m0-7 @k8, 24-31 -> m8-15 @k8
    const int a_row  = wm*64 + (lane & 15);
    const int a_colh = ((lane >> 4) & 1) * 8;
    // B (two n8xk16): lanes0-7 -> n0-7 @k0, 8-15 -> n0-7 @k8, 16-23 -> n8-15 @k0, 24-31 -> n8-15 @k8
    const int b_row  = wn*32 + (lane & 7) + ((lane & 16) >> 1);
    const int b_colh = ((lane >> 3) & 1) * 8;
    uint32_t a_base[STAGES], b_base[STAGES];
    #pragma unroll
    for (int s = 0; s < STAGES; s++) {
        a_base[s] = (uint32_t)__cvta_generic_to_shared(&As[s][a_row][a_colh]);
        b_base[s] = (uint32_t)__cvta_generic_to_shared(&Ws[s][b_row][b_colh]);
    }

    for (int kt = 0; kt < KT; kt++) {
        const int cur = kt % STAGES;
        asm volatile("cp.async.wait_group 1;");
        __syncthreads();

        if (kt + 2 < KT) {
            const int nb = (kt + 2) % STAGES;
            const int ko = (kt + 2) << 5;
            if (aok) { cp16(&As[nb][srow][scol], Ap + ko); cp16(&As[nb][srow][scol+8], Ap + ko + 8); }
            cp16(&Ws[nb][srow][scol], Wp + ko); cp16(&Ws[nb][srow][scol+8], Wp + ko + 8);
            asm volatile("cp.async.commit_group;");
        }

        #pragma unroll
        for (int kh = 0; kh < 2; kh++) {            // two k16 halves of BK=32
            uint32_t af[4][4], bf[2][4];
            #pragma unroll
            for (int mt = 0; mt < 4; mt++)
                ldsm4(af[mt], a_base[cur] + (uint32_t)((kh*16 + mt*16*HPITCH) * 2));
            #pragma unroll
            for (int pr = 0; pr < 2; pr++)
                ldsm4(bf[pr], b_base[cur] + (uint32_t)((kh*16 + pr*16*HPITCH) * 2));
            #pragma unroll
            for (int mt = 0; mt < 4; mt++)
                #pragma unroll
                for (int nt = 0; nt < 4; nt++)
                    mma_h(acc[mt][nt], af[mt], &bf[nt>>1][(nt&1)*2]);
        }
        __syncthreads();
    }

    // epilogue (acc layout: lane>>2 -> row, rows +0/+8; cols 2*(lane&3)+{0,1})
    const int cn = bn + wn*32;
    float bv[4][2];
    #pragma unroll
    for (int nt = 0; nt < 4; nt++) {
        int c = cn + nt*8 + 2*(lane & 3);
        bv[nt][0] = bias[c];
        bv[nt][1] = bias[c+1];
    }
    #pragma unroll
    for (int mt = 0; mt < 4; mt++) {
        const int r0 = bm + wm*64 + mt*16 + (lane >> 2);
        #pragma unroll
        for (int half = 0; half < 2; half++) {
            const int r = r0 + half*8;
            if (r < M) {
                #pragma unroll
                for (int nt = 0; nt < 4; nt++) {
                    float x0 = acc[mt][nt][half*2+0] + bv[nt][0];
                    float x1 = acc[mt][nt][half*2+1] + bv[nt][1];
                    if (ACT) { x0 = gelu_t(x0); x1 = gelu_t(x1); }
                    const size_t off = (size_t)r*N + cn + nt*8 + 2*(lane & 3);
                    if (MODE == 0) {
                        *(float2*)&C[off] = make_float2(x0, x1);
                    } else if (MODE == 1) {
                        *(__half2*)&Ch[off] = __floats2half2_rn(x0, x1);
                    } else {
                        *(float2*)&C[off]   = make_float2(x0, x1);
                        *(__half2*)&Ch[off] = __floats2half2_rn(x0, x1);
                    }
                }
            }
        }
    }
}

// ---------------------------------------------------------------------------
// out[row] = hid[row] + a*(x-mean)/(std(ddof=1)+eps) + b
// ---------------------------------------------------------------------------
__global__ void __launch_bounds__(128) ln_res_kernel(
    const float* __restrict__ hid, const float* __restrict__ ffn,
    const float* __restrict__ ga,  const float* __restrict__ gb,
    float* __restrict__ out)
{
    const int row = blockIdx.x;
    const int tid = threadIdx.x;
    float4 xv = ((const float4*)(ffn + (size_t)row*D_))[tid];
    float s = xv.x + xv.y + xv.z + xv.w;
    float q = xv.x*xv.x + xv.y*xv.y + xv.z*xv.z + xv.w*xv.w;
    #pragma unroll
    for (int o = 16; o > 0; o >>= 1) {
        s += __shfl_xor_sync(0xffffffffu, s, o);
        q += __shfl_xor_sync(0xffffffffu, q, o);
    }
    __shared__ float ss[4], sq[4];
    if ((tid & 31) == 0) { ss[tid>>5] = s; sq[tid>>5] = q; }
    __syncthreads();
    float S = ss[0]+ss[1]+ss[2]+ss[3];
    float Q = sq[0]+sq[1]+sq[2]+sq[3];
    float mean = S * (1.f/D_);
    float var  = (Q - (float)D_*mean*mean) * (1.f/(D_-1));
    var = fmaxf(var, 0.f);
    float inv = 1.f / (sqrtf(var) + 1e-6f);

    float4 hv = ((const float4*)(hid + (size_t)row*D_))[tid];
    float4 av = ((const float4*)ga)[tid];
    float4 bv = ((const float4*)gb)[tid];
    float4 o4;
    o4.x = hv.x + av.x*(xv.x-mean)*inv + bv.x;
    o4.y = hv.y + av.y*(xv.y-mean)*inv + bv.y;
    o4.z = hv.z + av.z*(xv.z-mean)*inv + bv.z;
    o4.w = hv.w + av.w*(xv.w-mean)*inv + bv.w;
    ((float4*)(out + (size_t)row*D_))[tid] = o4;
}

// ---------------------------------------------------------------------------
extern "C" void kernel_launch(void* const* d_in, const int* in_sizes, int n_in,
                              void* d_out, int out_size)
{
    const float* img    = (const float*)d_in[0];
    const float* title  = (const float*)d_in[1];
    const int*   mask   = (const int*)  d_in[2];
    const float* s_img  = (const float*)d_in[3];
    const float* s_tit  = (const float*)d_in[4];
    const float* w_proj = (const float*)d_in[5];
    const float* b_proj = (const float*)d_in[6];
    const float* w1i    = (const float*)d_in[7];
    const float* b1i    = (const float*)d_in[8];
    const float* w2i    = (const float*)d_in[9];
    const float* b2i    = (const float*)d_in[10];
    const float* w1t    = (const float*)d_in[11];
    const float* b1t    = (const float*)d_in[12];
    const float* w2t    = (const float*)d_in[13];
    const float* b2t    = (const float*)d_in[14];
    const float* lai    = (const float*)d_in[15];
    const float* lbi    = (const float*)d_in[16];
    const float* lat    = (const float*)d_in[17];
    const float* lbt    = (const float*)d_in[18];
    float* out = (float*)d_out;

    __half *attn, *hidh, *ffh, *wph, *w1ih, *w2ih, *w1th, *w2th;
    float *hid, *ffo;
    cudaGetSymbolAddress((void**)&attn, g_attn);
    cudaGetSymbolAddress((void**)&hid,  g_hid);
    cudaGetSymbolAddress((void**)&hidh, g_hidh);
    cudaGetSymbolAddress((void**)&ffh,  g_ffh);
    cudaGetSymbolAddress((void**)&ffo,  g_ffo);
    cudaGetSymbolAddress((void**)&wph,  g_wph);
    cudaGetSymbolAddress((void**)&w1ih, g_w1ih);
    cudaGetSymbolAddress((void**)&w2ih, g_w2ih);
    cudaGetSymbolAddress((void**)&w1th, g_w1th);
    cudaGetSymbolAddress((void**)&w2th, g_w2th);

    // weight fp16 conversion (~9MB writes)
    to_half_kernel<<<256, 256>>>(w_proj, wph, D_*D_/4);
    to_half_kernel<<<512, 256>>>(w1i, w1ih, DFF_*D_/4);
    to_half_kernel<<<512, 256>>>(w2i, w2ih, D_*DFF_/4);
    to_half_kernel<<<512, 256>>>(w1t, w1th, DFF_*D_/4);
    to_half_kernel<<<512, 256>>>(w2t, w2th, D_*DFF_/4);

    attn_kernel<<<B_*L_*H_, 256>>>(img, title, mask, s_img, s_tit, attn);

    dim3 gP(D_/128, (ROWS_ALL+127)/128);
    gemm_h<0,2><<<gP, 256>>>(attn, wph, b_proj, hid, hidh, ROWS_ALL, D_, D_);

    dim3 g1i(DFF_/128, (ROWS_IMG+127)/128);
    gemm_h<1,1><<<g1i, 256>>>(hidh, w1ih, b1i, (float*)0, ffh, ROWS_IMG, DFF_, D_);
    dim3 g2i(D_/128, (ROWS_IMG+127)/128);
    gemm_h<0,0><<<g2i, 256>>>(ffh, w2ih, b2i, ffo, (__half*)0, ROWS_IMG, D_, DFF_);
    ln_res_kernel<<<ROWS_IMG, 128>>>(hid, ffo, lai, lbi, out);

    const __half* hidhT = hidh + (size_t)ROWS_IMG*D_;
    dim3 g1t(DFF_/128, (ROWS_TIT+127)/128);
    gemm_h<1,1><<<g1t, 256>>>(hidhT, w1th, b1t, (float*)0, ffh, ROWS_TIT, DFF_, D_);
    dim3 g2t(D_/128, (ROWS_TIT+127)/128);
    gemm_h<0,0><<<g2t, 256>>>(ffh, w2th, b2t, ffo, (__half*)0, ROWS_TIT, D_, DFF_);
    ln_res_kernel<<<ROWS_TIT, 128>>>(hid + (size_t)ROWS_IMG*D_, ffo, lat, lbt,
                                     out + (size_t)ROWS_IMG*D_);
}